// round 13
// baseline (speedup 1.0000x reference)
#include <cuda_runtime.h>
#include <cuda_bf16.h>
#include <cuda_fp16.h>
#include <math.h>
#include <stdint.h>

#define BSZ   8
#define LSEQ  2048
#define HDIM  512
#define NST   64
#define ROWS  (BSZ*LSEQ)      // 16384
#define SEG   16
#define SEGT  (LSEQ/SEG)      // 128

typedef __half fp16;
typedef __half2 fp162;

// ---------------- scratch ----------------------------------------------------------
__device__ float g_wre[HDIM*NST];
__device__ float g_wim[HDIM*NST];
__device__ float g_wTre[HDIM*NST];
__device__ float g_wTim[HDIM*NST];
__device__ float g_ctre[HDIM*NST];
__device__ float g_ctim[HDIM*NST];

__device__ float g_xT[(size_t)ROWS*HDIM];             // x transposed to (B, H, L)

__device__ float g_sendre[(size_t)BSZ*HDIM*SEG*NST];
__device__ float g_sendim[(size_t)BSZ*HDIM*SEG*NST];
__device__ float g_carre [(size_t)BSZ*HDIM*SEG*NST];
__device__ float g_carim [(size_t)BSZ*HDIM*SEG*NST];

__device__ fp16  g_yf [(size_t)ROWS*HDIM];   // S4 activation (fp16)
__device__ float g_z  [(size_t)ROWS*2*HDIM];
__device__ float g_xln[(size_t)ROWS*HDIM];
__device__ fp16  g_xf [(size_t)ROWS*HDIM];   // xln (fp16)
__device__ fp16  g_y1f[(size_t)ROWS*HDIM];   // FFN hidden (fp16)
__device__ float g_y2 [(size_t)ROWS*HDIM];

__device__ fp16 g_woutf[2*HDIM*HDIM];
__device__ fp16 g_w1f[HDIM*HDIM];
__device__ fp16 g_w2f[HDIM*HDIM];

// =============================== helpers =========================================
__device__ __forceinline__ uint32_t smem_u32(const void* p) {
    uint32_t a;
    asm("{ .reg .u64 t; cvta.to.shared.u64 t, %1; cvt.u32.u64 %0, t; }" : "=r"(a) : "l"(p));
    return a;
}

__device__ __forceinline__ void ldmatrix_x4(uint32_t* r, uint32_t addr) {
    asm volatile("ldmatrix.sync.aligned.m8n8.x4.shared.b16 {%0,%1,%2,%3}, [%4];"
        : "=r"(r[0]), "=r"(r[1]), "=r"(r[2]), "=r"(r[3]) : "r"(addr));
}

__device__ __forceinline__ void mma_f16(float* c, const uint32_t* a,
                                        uint32_t b0, uint32_t b1) {
    asm volatile("mma.sync.aligned.m16n8k16.row.col.f32.f16.f16.f32 "
        "{%0,%1,%2,%3}, {%4,%5,%6,%7}, {%8,%9}, {%0,%1,%2,%3};"
        : "+f"(c[0]), "+f"(c[1]), "+f"(c[2]), "+f"(c[3])
        : "r"(a[0]), "r"(a[1]), "r"(a[2]), "r"(a[3]), "r"(b0), "r"(b1));
}

#define CP_ASYNC16(saddr, gaddr) \
    asm volatile("cp.async.cg.shared.global [%0], [%1], 16;" \
                 :: "r"(saddr), "l"(gaddr) : "memory")
#define CP_COMMIT() asm volatile("cp.async.commit_group;" ::: "memory")
#define CP_WAIT(n)  asm volatile("cp.async.wait_group %0;" :: "n"(n) : "memory")

// ---- packed f32x2 ops (Blackwell) ----
__device__ __forceinline__ uint64_t pk2(float lo, float hi) {
    uint64_t r; asm("mov.b64 %0, {%1,%2};" : "=l"(r) : "f"(lo), "f"(hi)); return r;
}
__device__ __forceinline__ void upk2(uint64_t v, float& lo, float& hi) {
    asm("mov.b64 {%0,%1}, %2;" : "=f"(lo), "=f"(hi) : "l"(v));
}
__device__ __forceinline__ uint64_t fma2(uint64_t a, uint64_t b, uint64_t c) {
    uint64_t d; asm("fma.rn.f32x2 %0, %1, %2, %3;" : "=l"(d) : "l"(a), "l"(b), "l"(c)); return d;
}
__device__ __forceinline__ uint64_t mul2(uint64_t a, uint64_t b) {
    uint64_t d; asm("mul.rn.f32x2 %0, %1, %2;" : "=l"(d) : "l"(a), "l"(b)); return d;
}
__device__ __forceinline__ uint64_t add2(uint64_t a, uint64_t b) {
    uint64_t d; asm("add.rn.f32x2 %0, %1, %2;" : "=l"(d) : "l"(a), "l"(b)); return d;
}

// ---------------- x transpose: (B,L,H) -> (B,H,L) ---------------------------------
__global__ __launch_bounds__(256) void transpose_kernel(const float* __restrict__ x,
                                                        float* __restrict__ xT) {
    __shared__ float tile[32][33];
    int b  = blockIdx.z;
    int l0 = blockIdx.x * 32, h0 = blockIdx.y * 32;
    int tx = threadIdx.x & 31, ty = threadIdx.x >> 5;
    const float* xp = x + (size_t)b * LSEQ * HDIM;
#pragma unroll
    for (int i = 0; i < 32; i += 8)
        tile[ty + i][tx] = xp[(size_t)(l0 + ty + i) * HDIM + h0 + tx];
    __syncthreads();
    float* op = xT + (size_t)b * HDIM * LSEQ;
#pragma unroll
    for (int i = 0; i < 32; i += 8)
        op[(size_t)(h0 + ty + i) * LSEQ + l0 + tx] = tile[tx][ty + i];
}

// ---------------- weight convert (fp32 -> fp16, all three) -------------------------
__global__ void convert_w_kernel(const float* __restrict__ wout,
                                 const float* __restrict__ w1,
                                 const float* __restrict__ w2) {
    int i = blockIdx.x * blockDim.x + threadIdx.x;
    const int n1 = 2 * HDIM * HDIM;
    const int n2 = HDIM * HDIM;
    if (i < n1) {
        g_woutf[i] = __float2half_rn(wout[i]);
    } else if (i < n1 + n2) {
        g_w1f[i - n1] = __float2half_rn(w1[i - n1]);
    } else {
        g_w2f[i - n1 - n2] = __float2half_rn(w2[i - n1 - n2]);
    }
}

// ---------------- precompute -------------------------------------------------------
__global__ void precompute_kernel(const float* __restrict__ log_dt,
                                  const float* __restrict__ Are,
                                  const float* __restrict__ Aim,
                                  const float* __restrict__ Cre,
                                  const float* __restrict__ Cim) {
    int h = blockIdx.x, n = threadIdx.x;
    int idx = h * NST + n;
    float dt = expf(log_dt[h]);
    float ar = Are[idx] * dt;
    float ai = Aim[idx] * dt;
    float e  = expf(ar);
    float sb, cb;
    sincosf(ai, &sb, &cb);
    float wre = e * cb, wim = e * sb;
    float eT = expf(ar * (float)SEGT);
    float sT, cT;
    sincosf(ai * (float)SEGT, &sT, &cT);
    g_wTre[idx] = eT * cT;
    g_wTim[idx] = eT * sT;

    float Ere = wre - 1.0f, Eim = wim;
    float Ar = Are[idx], Ai = Aim[idx];
    float inv = 1.0f / (Ar * Ar + Ai * Ai);
    float rre = (Ere * Ar + Eim * Ai) * inv;
    float rim = (Eim * Ar - Ere * Ai) * inv;
    float cr = Cre[idx], ci = Cim[idx];
    g_ctre[idx] = cr * rre - ci * rim;
    g_ctim[idx] = cr * rim + ci * rre;
    g_wre[idx]  = wre;
    g_wim[idx]  = wim;
}

// ---------------- scan pass 1: 16 lanes/group, 4 states/lane -----------------------
__global__ __launch_bounds__(256) void scan_part1(const float* __restrict__ xT) {
    int tid  = threadIdx.x;
    int gid  = blockIdx.x * 16 + (tid >> 4);
    int lane = tid & 15;
    int seg  = gid % (SEG - 1);
    int rem  = gid / (SEG - 1);
    int h = rem & (HDIM - 1);
    int b = rem >> 9;

    uint64_t wre01[2], wim01[2], nwim01[2], sre01[2], sim01[2];
    int base = h * NST + lane * 4;
#pragma unroll
    for (int p = 0; p < 2; p++) {
        float w0 = g_wre[base + 2*p], w1 = g_wre[base + 2*p + 1];
        float i0 = g_wim[base + 2*p], i1 = g_wim[base + 2*p + 1];
        wre01[p]  = pk2(w0, w1);
        wim01[p]  = pk2(i0, i1);
        nwim01[p] = pk2(-i0, -i1);
        sre01[p] = 0; sim01[p] = 0;
    }
    const float* xp = xT + ((size_t)(b * HDIM + h)) * LSEQ + seg * SEGT;

    float ucur = __ldg(xp + lane);
    for (int l0 = 0; l0 < SEGT; l0 += 16) {
        int ln = l0 + 16 + lane; if (ln > SEGT - 1) ln = SEGT - 1;
        float unext = __ldg(xp + ln);

        float ub[16];
#pragma unroll
        for (int k = 0; k < 16; k++) ub[k] = __shfl_sync(0xffffffffu, ucur, k, 16);

#pragma unroll
        for (int k = 0; k < 16; k++) {
            uint64_t u2 = pk2(ub[k], ub[k]);
#pragma unroll
            for (int p = 0; p < 2; p++) {
                uint64_t nr = fma2(wre01[p], sre01[p], fma2(nwim01[p], sim01[p], u2));
                uint64_t ni = fma2(wim01[p], sre01[p], mul2(wre01[p], sim01[p]));
                sre01[p] = nr; sim01[p] = ni;
            }
        }
        ucur = unext;
    }

    size_t ob = (((size_t)(b * HDIM + h) * SEG) + seg) * NST + lane * 4;
#pragma unroll
    for (int p = 0; p < 2; p++) {
        float r0, r1, i0, i1;
        upk2(sre01[p], r0, r1);
        upk2(sim01[p], i0, i1);
        g_sendre[ob + 2*p] = r0; g_sendre[ob + 2*p + 1] = r1;
        g_sendim[ob + 2*p] = i0; g_sendim[ob + 2*p + 1] = i1;
    }
}

// ---------------- combine ----------------------------------------------------------
__global__ __launch_bounds__(256) void scan_combine() {
    int idx = blockIdx.x * blockDim.x + threadIdx.x;
    int n = idx & (NST - 1);
    int rem = idx >> 6;
    int h = rem & (HDIM - 1);
    int b = rem >> 9;
    float wTre = g_wTre[h * NST + n];
    float wTim = g_wTim[h * NST + n];
    float cr = 0.0f, ci = 0.0f;
    size_t base = ((size_t)(b * HDIM + h) * SEG) * NST + n;
#pragma unroll
    for (int j = 0; j < SEG; j++) {
        g_carre[base + (size_t)j * NST] = cr;
        g_carim[base + (size_t)j * NST] = ci;
        if (j < SEG - 1) {
            float er = g_sendre[base + (size_t)j * NST];
            float ei = g_sendim[base + (size_t)j * NST];
            float nr = fmaf(wTre, cr, fmaf(-wTim, ci, er));
            float ni = fmaf(wTim, cr, fmaf(wTre, ci, ei));
            cr = nr; ci = ni;
        }
    }
}

// ---------------- scan pass 2: 16 h/block, smem-staged coalesced stores ------------
// block = 16 groups sharing (b, seg), consecutive h. Each 16-step batch stages a
// 16(l) x 16(h) fp16 tile in smem, then writes l-rows (32B contiguous per row).
__global__ __launch_bounds__(256) void scan_part2(const float* __restrict__ xT,
                                                  const float* __restrict__ Dskip,
                                                  fp16* __restrict__ yf) {
    __shared__ fp16 tile[16][18];
    int tid  = threadIdx.x;
    int lane = tid & 15;
    int gidx = tid >> 4;
    int seg  = blockIdx.x & 15;
    int rest = blockIdx.x >> 4;          // 0..255
    int h0   = (rest & 31) << 4;
    int b    = rest >> 5;
    int h    = h0 + gidx;

    uint64_t wre01[2], wim01[2], nwim01[2], cre01[2], ncim01[2], sre01[2], sim01[2];
    int base = h * NST + lane * 4;
    size_t cb = (((size_t)(b * HDIM + h) * SEG) + seg) * NST + lane * 4;
#pragma unroll
    for (int p = 0; p < 2; p++) {
        float w0 = g_wre[base + 2*p], w1 = g_wre[base + 2*p + 1];
        float i0 = g_wim[base + 2*p], i1 = g_wim[base + 2*p + 1];
        float c0 = g_ctre[base + 2*p], c1 = g_ctre[base + 2*p + 1];
        float d0 = g_ctim[base + 2*p], d1 = g_ctim[base + 2*p + 1];
        wre01[p]  = pk2(w0, w1);
        wim01[p]  = pk2(i0, i1);
        nwim01[p] = pk2(-i0, -i1);
        cre01[p]  = pk2(c0, c1);
        ncim01[p] = pk2(-d0, -d1);
        sre01[p] = pk2(g_carre[cb + 2*p], g_carre[cb + 2*p + 1]);
        sim01[p] = pk2(g_carim[cb + 2*p], g_carim[cb + 2*p + 1]);
    }
    float Dv = Dskip[h];
    const float* xp = xT + ((size_t)(b * HDIM + h)) * LSEQ + seg * SEGT;
    size_t obase = ((size_t)b * LSEQ + seg * SEGT) * HDIM + h0;

    bool l1 = (lane & 1), l2 = (lane & 2), l4 = (lane & 4), l8 = (lane & 8);
    int orow = tid >> 4, ocol = tid & 15;    // output mapping

    float ucur = __ldg(xp + lane);
    for (int l0 = 0; l0 < SEGT; l0 += 16) {
        int ln = l0 + 16 + lane; if (ln > SEGT - 1) ln = SEGT - 1;
        float unext = __ldg(xp + ln);

        float buf[16];
#pragma unroll
        for (int k = 0; k < 16; k++) buf[k] = __shfl_sync(0xffffffffu, ucur, k, 16);

#pragma unroll
        for (int k = 0; k < 16; k++) {
            uint64_t u2 = pk2(buf[k], buf[k]);
            uint64_t accR, accI;
            {
                uint64_t nr = fma2(wre01[0], sre01[0], fma2(nwim01[0], sim01[0], u2));
                uint64_t ni = fma2(wim01[0], sre01[0], mul2(wre01[0], sim01[0]));
                sre01[0] = nr; sim01[0] = ni;
                accR = mul2(cre01[0], nr);
                accI = mul2(ncim01[0], ni);
            }
            {
                uint64_t nr = fma2(wre01[1], sre01[1], fma2(nwim01[1], sim01[1], u2));
                uint64_t ni = fma2(wim01[1], sre01[1], mul2(wre01[1], sim01[1]));
                sre01[1] = nr; sim01[1] = ni;
                accR = fma2(cre01[1], nr, accR);
                accI = fma2(ncim01[1], ni, accI);
            }
            uint64_t t = add2(accR, accI);
            float ta, tb; upk2(t, ta, tb);
            buf[k] = ta + tb;
        }

        // 4-stage recursive-halving transpose reduce over 16 lanes
        float q8[8], q4[4], q2[2], sfin;
#pragma unroll
        for (int j = 0; j < 8; j++) {
            float a = buf[2*j], bb = buf[2*j + 1];
            float sendv = l1 ? a : bb;
            float keepv = l1 ? bb : a;
            q8[j] = keepv + __shfl_xor_sync(0xffffffffu, sendv, 1, 16);
        }
#pragma unroll
        for (int j = 0; j < 4; j++) {
            float a = q8[2*j], bb = q8[2*j + 1];
            float sendv = l2 ? a : bb;
            float keepv = l2 ? bb : a;
            q4[j] = keepv + __shfl_xor_sync(0xffffffffu, sendv, 2, 16);
        }
#pragma unroll
        for (int j = 0; j < 2; j++) {
            float a = q4[2*j], bb = q4[2*j + 1];
            float sendv = l4 ? a : bb;
            float keepv = l4 ? bb : a;
            q2[j] = keepv + __shfl_xor_sync(0xffffffffu, sendv, 4, 16);
        }
        {
            float sendv = l8 ? q2[0] : q2[1];
            float keepv = l8 ? q2[1] : q2[0];
            sfin = keepv + __shfl_xor_sync(0xffffffffu, sendv, 8, 16);
        }

        float vv = fmaf(2.0f, sfin, Dv * ucur);
        float c = 0.7978845608028654f * (vv + 0.044715f * vv * vv * vv);
        float gv = vv / (1.0f + __expf(-2.0f * c));
        tile[lane][gidx] = __float2half_rn(gv);
        __syncthreads();
        yf[obase + (size_t)(l0 + orow) * HDIM + ocol] = tile[orow][ocol];
        __syncthreads();

        ucur = unext;
    }
}

// ============ mma.sync plain fp16 GEMM, 3-stage cp.async pipeline ==================
#define LDSB   80
#define TILEB  (128 * LDSB)
#define STAGEB (2 * TILEB)          // A, B
#define NSTAGE 3
#define GEMM_SMEM (NSTAGE * STAGEB) // 61440 bytes -> 2 CTAs/SM

__global__ void __launch_bounds__(256, 2)
gemm_mma(const fp16* __restrict__ A, const fp16* __restrict__ B,
         const float* __restrict__ bias,
         float* __restrict__ C, fp16* __restrict__ Cf,
         int K, int N, int mode) {   // mode 0: fp32 out; 1: relu + fp16 out
    extern __shared__ char smem[];
    uint32_t sbase = smem_u32(smem);
    int tid = threadIdx.x, wid = tid >> 5, lane = tid & 31;
    int row0 = blockIdx.y * 128, col0 = blockIdx.x * 128;
    int wm = wid >> 1, wn = wid & 1;

    float acc[2][8][4];
#pragma unroll
    for (int i = 0; i < 2; i++)
#pragma unroll
        for (int j = 0; j < 8; j++)
#pragma unroll
            for (int q = 0; q < 4; q++) acc[i][j][q] = 0.0f;

    int lr = tid >> 1;
    int lc = (tid & 1) * 16;
    const fp16* ap = A + (size_t)(row0 + lr) * K + lc;
    const fp16* bp = B + (size_t)(col0 + lr) * K + lc;
    uint32_t soff = (uint32_t)(lr * LDSB + lc * 2);

    int nch = K / 32;

    auto issue = [&](int c, int s) {
        uint32_t st = sbase + (uint32_t)s * STAGEB;
        int go = c * 32;
        uint32_t aa = st + soff;
        CP_ASYNC16(aa,      ap + go);
        CP_ASYNC16(aa + 16, ap + go + 8);
        uint32_t bb = st + TILEB + soff;
        CP_ASYNC16(bb,      bp + go);
        CP_ASYNC16(bb + 16, bp + go + 8);
    };

    issue(0, 0); CP_COMMIT();
    if (nch > 1) { issue(1, 1); CP_COMMIT(); }

    int r_lm = (lane & 7) + ((lane >> 3) & 1) * 8;
    int k_lm = ((lane >> 4) & 1) * 8;

    for (int c = 0; c < nch; ++c) {
        CP_WAIT(1);               // chunk c done; chunk c+1 may still be in flight
        __syncthreads();          // all warps done with stage (c) % NSTAGE reuse
        if (c + 2 < nch) {
            issue(c + 2, (c + 2) % NSTAGE);
            CP_COMMIT();
        }

        uint32_t st = sbase + (uint32_t)(c % NSTAGE) * STAGEB;

#pragma unroll
        for (int ks = 0; ks < 2; ++ks) {
            int kcol = ks * 16 + k_lm;
            uint32_t af[2][4];
#pragma unroll
            for (int mi = 0; mi < 2; ++mi) {
                int m = wm * 32 + mi * 16 + r_lm;
                ldmatrix_x4(af[mi], st + (uint32_t)(m * LDSB + kcol * 2));
            }
#pragma unroll
            for (int nj = 0; nj < 4; ++nj) {
                uint32_t bf[4];
                int n = wn * 64 + nj * 16 + r_lm;
                ldmatrix_x4(bf, st + TILEB + (uint32_t)(n * LDSB + kcol * 2));
#pragma unroll
                for (int mi = 0; mi < 2; ++mi)
#pragma unroll
                    for (int h = 0; h < 2; ++h)
                        mma_f16(acc[mi][nj * 2 + h], af[mi], bf[h], bf[2 + h]);
            }
        }
    }

    int tg = lane >> 2, tq = lane & 3;
#pragma unroll
    for (int mi = 0; mi < 2; ++mi) {
        int r = row0 + wm * 32 + mi * 16 + tg;
#pragma unroll
        for (int ni = 0; ni < 8; ++ni) {
            int cix = col0 + wn * 64 + ni * 8 + tq * 2;
            float b0 = bias[cix], b1 = bias[cix + 1];
            float v0 = acc[mi][ni][0] + b0, v1 = acc[mi][ni][1] + b1;
            float v2 = acc[mi][ni][2] + b0, v3 = acc[mi][ni][3] + b1;
            if (mode == 0) {
                *(float2*)(C + (size_t)r * N + cix) = make_float2(v0, v1);
                *(float2*)(C + (size_t)(r + 8) * N + cix) = make_float2(v2, v3);
            } else {
                v0 = fmaxf(v0, 0.0f); v1 = fmaxf(v1, 0.0f);
                v2 = fmaxf(v2, 0.0f); v3 = fmaxf(v3, 0.0f);
                *(fp162*)(Cf + (size_t)r * N + cix) = __floats2half2_rn(v0, v1);
                *(fp162*)(Cf + (size_t)(r + 8) * N + cix) = __floats2half2_rn(v2, v3);
            }
        }
    }
}

// ---------------- block reduce helper ---------------------------------------------
__device__ __forceinline__ float2 block_reduce_2(float a, float b) {
    unsigned m = 0xffffffffu;
#pragma unroll
    for (int o = 16; o > 0; o >>= 1) {
        a += __shfl_down_sync(m, a, o);
        b += __shfl_down_sync(m, b, o);
    }
    __shared__ float sa[4], sb[4];
    int w = threadIdx.x >> 5, lane = threadIdx.x & 31;
    if (lane == 0) { sa[w] = a; sb[w] = b; }
    __syncthreads();
    if (threadIdx.x == 0) {
        float ta = sa[0] + sa[1] + sa[2] + sa[3];
        float tb = sb[0] + sb[1] + sb[2] + sb[3];
        sa[0] = ta; sb[0] = tb;
    }
    __syncthreads();
    return make_float2(sa[0], sb[0]);
}

// ---------------- GLU + residual + LN1 (fp32 + fp16 out) ---------------------------
__global__ __launch_bounds__(128) void glu_ln_kernel(const float* __restrict__ z,
                                                     const float* __restrict__ x,
                                                     const float* __restrict__ g1,
                                                     const float* __restrict__ b1,
                                                     float* __restrict__ xln,
                                                     fp16* __restrict__ xf) {
    int row = blockIdx.x, tid = threadIdx.x;
    const float4* zr = (const float4*)(z + (size_t)row * (2 * HDIM));
    const float4* xr = (const float4*)(x + (size_t)row * HDIM);
    float4 a = zr[tid];
    float4 g = zr[tid + 128];
    float4 xv = xr[tid];
    float4 v;
    v.x = xv.x + a.x / (1.0f + __expf(-g.x));
    v.y = xv.y + a.y / (1.0f + __expf(-g.y));
    v.z = xv.z + a.z / (1.0f + __expf(-g.z));
    v.w = xv.w + a.w / (1.0f + __expf(-g.w));
    float s  = v.x + v.y + v.z + v.w;
    float s2 = v.x*v.x + v.y*v.y + v.z*v.z + v.w*v.w;
    float2 tot = block_reduce_2(s, s2);
    float mu = tot.x * (1.0f / HDIM);
    float var = tot.y * (1.0f / HDIM) - mu * mu;
    float rstd = rsqrtf(var + 1e-5f);
    float4 gv = ((const float4*)g1)[tid];
    float4 bv = ((const float4*)b1)[tid];
    float4 o;
    o.x = (v.x - mu) * rstd * gv.x + bv.x;
    o.y = (v.y - mu) * rstd * gv.y + bv.y;
    o.z = (v.z - mu) * rstd * gv.z + bv.z;
    o.w = (v.w - mu) * rstd * gv.w + bv.w;
    ((float4*)(xln + (size_t)row * HDIM))[tid] = o;
    fp162* xf2 = (fp162*)(xf + (size_t)row * HDIM);
    xf2[tid*2]   = __floats2half2_rn(o.x, o.y);
    xf2[tid*2+1] = __floats2half2_rn(o.z, o.w);
}

// ---------------- residual + LN2 (float4) -------------------------------------------
__global__ __launch_bounds__(128) void final_ln_kernel(const float* __restrict__ xln,
                                                       const float* __restrict__ y2,
                                                       const float* __restrict__ g2,
                                                       const float* __restrict__ b2,
                                                       float* __restrict__ out) {
    int row = blockIdx.x, tid = threadIdx.x;
    float4 a = ((const float4*)(xln + (size_t)row * HDIM))[tid];
    float4 b = ((const float4*)(y2  + (size_t)row * HDIM))[tid];
    float4 v;
    v.x = a.x + b.x; v.y = a.y + b.y; v.z = a.z + b.z; v.w = a.w + b.w;
    float s  = v.x + v.y + v.z + v.w;
    float s2 = v.x*v.x + v.y*v.y + v.z*v.z + v.w*v.w;
    float2 tot = block_reduce_2(s, s2);
    float mu = tot.x * (1.0f / HDIM);
    float var = tot.y * (1.0f / HDIM) - mu * mu;
    float rstd = rsqrtf(var + 1e-5f);
    float4 gv = ((const float4*)g2)[tid];
    float4 bv = ((const float4*)b2)[tid];
    float4 o;
    o.x = (v.x - mu) * rstd * gv.x + bv.x;
    o.y = (v.y - mu) * rstd * gv.y + bv.y;
    o.z = (v.z - mu) * rstd * gv.z + bv.z;
    o.w = (v.w - mu) * rstd * gv.w + bv.w;
    ((float4*)(out + (size_t)row * HDIM))[tid] = o;
}

// ---------------- launch ------------------------------------------------------------
extern "C" void kernel_launch(void* const* d_in, const int* in_sizes, int n_in,
                              void* d_out, int out_size) {
    const float* x      = (const float*)d_in[0];
    const float* log_dt = (const float*)d_in[1];
    const float* A_re   = (const float*)d_in[2];
    const float* A_im   = (const float*)d_in[3];
    const float* C_re   = (const float*)d_in[4];
    const float* C_im   = (const float*)d_in[5];
    const float* D_skip = (const float*)d_in[6];
    const float* W_out  = (const float*)d_in[7];
    const float* b_out  = (const float*)d_in[8];
    const float* g1     = (const float*)d_in[9];
    const float* beta1  = (const float*)d_in[10];
    const float* g2     = (const float*)d_in[11];
    const float* beta2  = (const float*)d_in[12];
    const float* W1     = (const float*)d_in[13];
    const float* bc1    = (const float*)d_in[14];
    const float* W2     = (const float*)d_in[15];
    const float* bc2    = (const float*)d_in[16];
    float* out = (float*)d_out;

    fp16 *yf, *xf, *y1f, *woutf, *w1f, *w2f;
    float *z, *xln, *y2, *xT;
    cudaGetSymbolAddress((void**)&yf,  g_yf);
    cudaGetSymbolAddress((void**)&z,   g_z);
    cudaGetSymbolAddress((void**)&xln, g_xln);
    cudaGetSymbolAddress((void**)&xf,  g_xf);
    cudaGetSymbolAddress((void**)&y1f, g_y1f);
    cudaGetSymbolAddress((void**)&y2,  g_y2);
    cudaGetSymbolAddress((void**)&xT,  g_xT);
    cudaGetSymbolAddress((void**)&woutf, g_woutf);
    cudaGetSymbolAddress((void**)&w1f, g_w1f);
    cudaGetSymbolAddress((void**)&w2f, g_w2f);

    cudaFuncSetAttribute(gemm_mma, cudaFuncAttributeMaxDynamicSharedMemorySize, GEMM_SMEM);

    precompute_kernel<<<HDIM, NST>>>(log_dt, A_re, A_im, C_re, C_im);
    transpose_kernel<<<dim3(LSEQ / 32, HDIM / 32, BSZ), 256>>>(x, xT);

    scan_part1<<<(BSZ * HDIM * (SEG - 1)) / 16, 256>>>(xT);
    scan_combine<<<(BSZ * HDIM * NST) / 256, 256>>>();
    scan_part2<<<BSZ * (HDIM / 16) * SEG, 256>>>(xT, D_skip, yf);

    convert_w_kernel<<<(4 * HDIM * HDIM + 255) / 256, 256>>>(W_out, W1, W2);

    gemm_mma<<<dim3((2 * HDIM) / 128, ROWS / 128), 256, GEMM_SMEM>>>(
        yf, woutf, b_out, z, nullptr, HDIM, 2 * HDIM, 0);

    glu_ln_kernel<<<ROWS, 128>>>(z, x, g1, beta1, xln, xf);

    gemm_mma<<<dim3(HDIM / 128, ROWS / 128), 256, GEMM_SMEM>>>(
        xf, w1f, bc1, nullptr, y1f, HDIM, HDIM, 1);

    gemm_mma<<<dim3(HDIM / 128, ROWS / 128), 256, GEMM_SMEM>>>(
        y1f, w2f, bc2, y2, nullptr, HDIM, HDIM, 0);

    final_ln_kernel<<<ROWS, 128>>>(xln, y2, g2, beta2, out);
}